// round 1
// baseline (speedup 1.0000x reference)
#include <cuda_runtime.h>
#include <stdint.h>

// Remap embeddings: out[b, slot, :] = embeddings[i] where slot = rank of i
// within its (sorted) position group; remaining slots are zero.
// Because positions are sorted and slots are ranks, each output row is a
// CONTIGUOUS copy of emb[start*EMB : end*EMB] followed by a zero tail.

#define EMB 64
#define HIST 50
#define ROW_F4 (HIST * EMB / 4)   // 800 float4 per output row
#define ENT_F4 (EMB / 4)          // 16 float4 per embedding entry

__global__ void __launch_bounds__(256) remap_kernel(
    const float4* __restrict__ emb,
    const int*    __restrict__ pos,
    int n_valid,
    float4* __restrict__ out)
{
    const int b = blockIdx.x;

    // lower_bound(pos, b) -> start ; lower_bound(pos, b+1) -> end
    // All threads compute redundantly (uniform, L2-resident, ~19 probes).
    int lo = 0, hi = n_valid;
    while (lo < hi) {
        int mid = (lo + hi) >> 1;
        if (pos[mid] < b) lo = mid + 1; else hi = mid;
    }
    const int start = lo;
    hi = n_valid;
    while (lo < hi) {
        int mid = (lo + hi) >> 1;
        if (pos[mid] < b + 1) lo = mid + 1; else hi = mid;
    }
    const int end = lo;

    int cnt_f4 = (end - start) * ENT_F4;        // occupied float4 in this row
    if (cnt_f4 > ROW_F4) cnt_f4 = ROW_F4;       // mode="drop" clamp

    float4* __restrict__ orow = out + (size_t)b * ROW_F4;
    const float4* __restrict__ irow = emb + (size_t)start * ENT_F4;
    const float4 zero = make_float4(0.f, 0.f, 0.f, 0.f);

    #pragma unroll 4
    for (int v = threadIdx.x; v < ROW_F4; v += 256) {
        orow[v] = (v < cnt_f4) ? irow[v] : zero;
    }
}

extern "C" void kernel_launch(void* const* d_in, const int* in_sizes, int n_in,
                              void* d_out, int out_size)
{
    const float4* emb = (const float4*)d_in[0];
    const int*    pos = (const int*)d_in[1];
    const int n_valid = in_sizes[1];

    // batch rows from output size (out = batch * HIST * EMB floats)
    const int batch = out_size / (HIST * EMB);

    remap_kernel<<<batch, 256>>>(emb, pos, n_valid, (float4*)d_out);
}

// round 3
// speedup vs baseline: 2.2460x; 2.2460x over previous
#include <cuda_runtime.h>
#include <stdint.h>

#define EMB 64
#define HIST 50
#define ROW_F4 (HIST * EMB / 4)   // 800 float4 per output row
#define ENT_F4 (EMB / 4)          // 16 float4 per embedding entry
#define MAX_BATCH (1 << 21)       // scratch capacity (rows + 1 sentinel)

// Static scratch: row_start[b] = first index i with pos[i] >= b.
// row_start[batch] = n_valid (sentinel).
__device__ int g_row_start[MAX_BATCH + 1];

// Kernel 1: compute group boundaries directly from the sorted positions.
// Thread i (0..n_valid inclusive) handles boundary between pos[i-1] and pos[i].
__global__ void __launch_bounds__(256) boundaries_kernel(
    const int* __restrict__ pos, int n_valid, int batch)
{
    int i = blockIdx.x * blockDim.x + threadIdx.x;
    if (i > n_valid) return;
    int cur  = (i < n_valid) ? pos[i]     : batch;
    int prev = (i > 0)       ? pos[i - 1] : -1;
    // start[b] = i for all rows b in (prev, cur]  (typically 0 or 1 iteration)
    for (int b = prev + 1; b <= cur; b++) {
        if (b <= batch) g_row_start[b] = i;
    }
    if (i == 0) g_row_start[0] = 0;
}

// Kernel 2: pure streaming copy. out[b] = emb[start:end] ++ zeros.
__global__ void __launch_bounds__(256) remap_kernel(
    const float4* __restrict__ emb,
    float4* __restrict__ out)
{
    const int b = blockIdx.x;
    const int start = g_row_start[b];
    const int end   = g_row_start[b + 1];

    int cnt_f4 = (end - start) * ENT_F4;
    if (cnt_f4 > ROW_F4) cnt_f4 = ROW_F4;   // mode="drop" clamp

    float4* __restrict__ orow = out + (size_t)b * ROW_F4;
    const float4* __restrict__ irow = emb + (size_t)start * ENT_F4;
    const float4 zero = make_float4(0.f, 0.f, 0.f, 0.f);

    #pragma unroll 4
    for (int v = threadIdx.x; v < ROW_F4; v += 256) {
        float4 val = (v < cnt_f4) ? __ldcs(&irow[v]) : zero;
        __stcs(&orow[v], val);
    }
}

extern "C" void kernel_launch(void* const* d_in, const int* in_sizes, int n_in,
                              void* d_out, int out_size)
{
    const float4* emb = (const float4*)d_in[0];
    const int*    pos = (const int*)d_in[1];
    const int n_valid = in_sizes[1];
    const int batch   = out_size / (HIST * EMB);

    int bthreads = n_valid + 1;
    boundaries_kernel<<<(bthreads + 255) / 256, 256>>>(pos, n_valid, batch);
    remap_kernel<<<batch, 256>>>(emb, (float4*)d_out);
}